// round 9
// baseline (speedup 1.0000x reference)
#include <cuda_runtime.h>
#include <cstdint>

#define MROWS  16384
#define INDIM  1024
#define HDIM   512
#define DDIM   256
#define KCODES 4096
#define ODIM   1024

typedef unsigned long long u64;

// ---------------- scratch (static device globals; no allocations) ----------
__device__ float g_h[(size_t)MROWS * HDIM];      // h = z @ W_qa + b_qa
__device__ float g_hT[(size_t)HDIM * MROWS];     // h transposed [kk][m]
__device__ float g_zT[(size_t)INDIM * MROWS];    // z transposed [k][m]
__device__ float g_zqT[(size_t)HDIM * MROWS];    // zq_st transposed [kk][m]
__device__ float g_eTd[2][DDIM][2 * KCODES];     // emb transposed + duplicated [half][k][2n]
__device__ float g_W1d[INDIM][2 * HDIM];         // W_qa duplicated [k][2n]
__device__ float g_W2d[HDIM][2 * ODIM];          // W_pq duplicated [k][2n]
__device__ float g_a[2][MROWS];                  // |z_half|^2 per row
__device__ float g_bn[2][KCODES];                // |emb_k|^2 per code
__device__ int   g_idx[2][MROWS];                // argmin indices
__device__ float g_p[2][MROWS];                  // winning squared distance

// ---------------- helpers ----------------
__device__ __forceinline__ u64 pk(float x, float y) {
    u64 r; asm("mov.b64 %0, {%1, %2};" : "=l"(r) : "f"(x), "f"(y)); return r;
}
__device__ __forceinline__ void upk(u64 v, float& x, float& y) {
    asm("mov.b64 {%0, %1}, %2;" : "=f"(x), "=f"(y) : "l"(v));
}
__device__ __forceinline__ void ffma2(u64& d, u64 a, u64 b) {
    asm("fma.rn.f32x2 %0, %1, %2, %0;" : "+l"(d) : "l"(a), "l"(b));
}
__device__ __forceinline__ uint32_t smem_u32(const void* p) {
    uint32_t a;
    asm("{ .reg .u64 t; cvta.to.shared.u64 t, %1; cvt.u32.u64 %0, t; }" : "=r"(a) : "l"(p));
    return a;
}
__device__ __forceinline__ void cp16(uint32_t dst, const void* src) {
    asm volatile("cp.async.ca.shared.global [%0], [%1], 16;" :: "r"(dst), "l"(src));
}
__device__ __forceinline__ void cp_commit() { asm volatile("cp.async.commit_group;"); }
template <int N> __device__ __forceinline__ void cp_wait() {
    asm volatile("cp.async.wait_group %0;" :: "n"(N));
}

// One k-slice: A = 8 raw floats (4 packed pairs, rows 2ip/2ip+1),
// B = 8 pre-duplicated pairs. Zero mov overhead.
__device__ __forceinline__ void fma_slice(u64 acc2[4][8],
                                          const float* __restrict__ Arow,
                                          const float* __restrict__ Brow) {
    ulonglong2 a01 = *(const ulonglong2*)(Arow);
    ulonglong2 a23 = *(const ulonglong2*)(Arow + 4);
    u64 av[4] = { a01.x, a01.y, a23.x, a23.y };
    ulonglong2 b01 = *(const ulonglong2*)(Brow);
    ulonglong2 b23 = *(const ulonglong2*)(Brow + 4);
    ulonglong2 b45 = *(const ulonglong2*)(Brow + 8);
    ulonglong2 b67 = *(const ulonglong2*)(Brow + 12);
    u64 bd[8] = { b01.x, b01.y, b23.x, b23.y, b45.x, b45.y, b67.x, b67.y };
#pragma unroll
    for (int ip = 0; ip < 4; ip++)
#pragma unroll
        for (int j = 0; j < 8; j++) ffma2(acc2[ip][j], av[ip], bd[j]);
}

// ---------------- prep kernels ----------------
__global__ void norms_kernel(const float* __restrict__ emb1,
                             const float* __restrict__ emb2) {
    int gw   = (blockIdx.x * blockDim.x + threadIdx.x) >> 5;
    int lane = threadIdx.x & 31;
    if (gw >= 2 * KCODES) return;
    int half = gw >> 12;
    int k    = gw & (KCODES - 1);
    const float* row = (half ? emb2 : emb1) + (size_t)k * DDIM;
    float s = 0.0f;
    for (int c = lane; c < DDIM; c += 32) { float v = row[c]; s = __fmaf_rn(v, v, s); }
#pragma unroll
    for (int o = 16; o; o >>= 1) s += __shfl_xor_sync(0xffffffffu, s, o);
    if (lane == 0) g_bn[half][k] = s;
}

__global__ void rownorm_kernel() {
    int gw   = (blockIdx.x * blockDim.x + threadIdx.x) >> 5;
    int lane = threadIdx.x & 31;
    if (gw >= MROWS) return;
    const float* row = g_h + (size_t)gw * HDIM;
#pragma unroll
    for (int half = 0; half < 2; half++) {
        float s = 0.0f;
        for (int c = lane; c < DDIM; c += 32) {
            float v = row[half * DDIM + c];
            s = __fmaf_rn(v, v, s);
        }
#pragma unroll
        for (int o = 16; o; o >>= 1) s += __shfl_xor_sync(0xffffffffu, s, o);
        if (lane == 0) g_a[half][gw] = s;
    }
}

__global__ void transposeH_kernel() {            // g_hT[kk][m] = g_h[m][kk]
    __shared__ float t[32][33];
    int m0 = blockIdx.x * 32, k0 = blockIdx.y * 32;
    int x = threadIdx.x, y = threadIdx.y;
#pragma unroll
    for (int r = 0; r < 32; r += 8)
        t[y + r][x] = g_h[(size_t)(m0 + y + r) * HDIM + k0 + x];
    __syncthreads();
#pragma unroll
    for (int r = 0; r < 32; r += 8)
        g_hT[(size_t)(k0 + y + r) * MROWS + m0 + x] = t[x][y + r];
}

__global__ void transposeZ_kernel(const float* __restrict__ z) {
    __shared__ float t[32][33];
    int m0 = blockIdx.x * 32, k0 = blockIdx.y * 32;
    int x = threadIdx.x, y = threadIdx.y;
#pragma unroll
    for (int r = 0; r < 32; r += 8)
        t[y + r][x] = z[(size_t)(m0 + y + r) * INDIM + k0 + x];
    __syncthreads();
#pragma unroll
    for (int r = 0; r < 32; r += 8)
        g_zT[(size_t)(k0 + y + r) * MROWS + m0 + x] = t[x][y + r];
}

// zq_st transposed: g_zqT[kk][m] = h + fp32(e - h)
__global__ void zqT_kernel(const float* __restrict__ emb1,
                           const float* __restrict__ emb2) {
    __shared__ float t[32][33];
    int m0 = blockIdx.x * 32, k0 = blockIdx.y * 32;
    int half = k0 >> 8;
    const float* E = half ? emb2 : emb1;
    int x = threadIdx.x, y = threadIdx.y;
#pragma unroll
    for (int r = 0; r < 32; r += 8) {
        int m = m0 + y + r;
        int idx = g_idx[half][m];
        float h = g_h[(size_t)m * HDIM + k0 + x];
        float e = E[(size_t)idx * DDIM + (k0 - half * DDIM) + x];
        t[y + r][x] = __fadd_rn(h, __fadd_rn(e, -h));
    }
    __syncthreads();
#pragma unroll
    for (int r = 0; r < 32; r += 8)
        g_zqT[(size_t)(k0 + y + r) * MROWS + m0 + x] = t[x][y + r];
}

// emb transposed + duplicated: g_eTd[half][k][2n] = g_eTd[half][k][2n+1] = emb[n][k]
__global__ void transposeEdup_kernel(const float* __restrict__ emb1,
                                     const float* __restrict__ emb2) {
    __shared__ float t[32][33];
    int n0 = blockIdx.x * 32, k0 = blockIdx.y * 32, half = blockIdx.z;
    const float* E = half ? emb2 : emb1;
    int x = threadIdx.x, y = threadIdx.y;
#pragma unroll
    for (int r = 0; r < 32; r += 8)
        t[y + r][x] = E[(size_t)(n0 + y + r) * DDIM + k0 + x];
    __syncthreads();
#pragma unroll
    for (int r = 0; r < 32; r += 8) {
        float v = t[x][y + r];
        *(float2*)&g_eTd[half][k0 + y + r][2 * (n0 + x)] = make_float2(v, v);
    }
}

__global__ void dupW1_kernel(const float* __restrict__ W) {   // [1024,512] -> dup
    int i = blockIdx.x * blockDim.x + threadIdx.x;
    if (i >= INDIM * HDIM) return;
    int k = i / HDIM, n = i % HDIM;
    float v = W[i];
    *(float2*)&g_W1d[k][2 * n] = make_float2(v, v);
}
__global__ void dupW2_kernel(const float* __restrict__ W) {   // [512,1024] -> dup
    int i = blockIdx.x * blockDim.x + threadIdx.x;
    if (i >= HDIM * ODIM) return;
    int k = i / ODIM, n = i % ODIM;
    float v = W[i];
    *(float2*)&g_W2d[k][2 * n] = make_float2(v, v);
}

// ---------------- unified pipelined GEMM: C = AT^T @ B + bias --------------
// Operands selected DEVICE-SIDE via SEL (host cannot take &__device__ symbols).
// SEL=0: AT=g_zT, Bd=g_W1d, C=g_h (K=INDIM, NT=HDIM)
// SEL=1: AT=g_zqT, Bd=g_W2d, C=arg  (K=HDIM, NT=ODIM)
// CTA tile 128x128, k-chunk 16. smem: (A 2048 + Bdup 4096) x2 = 48KB.
template <int K, int NT, int SEL>
__global__ __launch_bounds__(256, 2)
void gemm_pipe(const float* __restrict__ bias, float* __restrict__ Cout) {
    const float* __restrict__ AT = (SEL == 0) ? g_zT : g_zqT;
    const float* __restrict__ Bd = (SEL == 0) ? &g_W1d[0][0] : &g_W2d[0][0];
    float* __restrict__ C = (SEL == 0) ? g_h : Cout;

    __shared__ float sm[12288];
    const uint32_t smb = smem_u32(sm);
    const int tid = threadIdx.x;
    const int ty  = tid >> 4;
    const int tx  = tid & 15;
    const int m0  = blockIdx.x * 128;
    const int n0  = blockIdx.y * 128;
    const int NCH = K / 16;

    auto issue = [&](int c) {
        uint32_t base = smb + (uint32_t)((c & 1) * 6144) * 4;
#pragma unroll
        for (int i = 0; i < 2; i++) {
            int f = tid + i * 256; int k = f >> 5, c4 = f & 31;
            cp16(base + (uint32_t)(k * 128 + c4 * 4) * 4,
                 AT + (size_t)(c * 16 + k) * MROWS + m0 + c4 * 4);
        }
#pragma unroll
        for (int i = 0; i < 4; i++) {
            int f = tid + i * 256; int k = f >> 6, c4 = f & 63;
            cp16(base + (uint32_t)(2048 + k * 256 + c4 * 4) * 4,
                 Bd + (size_t)(c * 16 + k) * (2 * NT) + 2 * n0 + c4 * 4);
        }
        cp_commit();
    };

    u64 acc2[4][8];
    const u64 Z = pk(0.0f, 0.0f);
#pragma unroll
    for (int ip = 0; ip < 4; ip++)
#pragma unroll
        for (int j = 0; j < 8; j++) acc2[ip][j] = Z;

    issue(0);
    for (int c = 0; c < NCH; c++) {
        if (c + 1 < NCH) { issue(c + 1); cp_wait<1>(); } else { cp_wait<0>(); }
        __syncthreads();
        const float* buf = sm + (c & 1) * 6144;
#pragma unroll
        for (int k = 0; k < 16; k++)
            fma_slice(acc2, buf + k * 128 + ty * 8, buf + 2048 + k * 256 + tx * 16);
        __syncthreads();
    }

#pragma unroll
    for (int ip = 0; ip < 4; ip++) {
        float cx[8], cy[8];
#pragma unroll
        for (int j = 0; j < 8; j++) upk(acc2[ip][j], cx[j], cy[j]);
        int r0 = m0 + ty * 8 + 2 * ip;
#pragma unroll
        for (int j = 0; j < 8; j += 4) {
            int n = n0 + tx * 8 + j;
            float4 o0, o1;
            o0.x = cx[j+0] + bias[n+0]; o0.y = cx[j+1] + bias[n+1];
            o0.z = cx[j+2] + bias[n+2]; o0.w = cx[j+3] + bias[n+3];
            o1.x = cy[j+0] + bias[n+0]; o1.y = cy[j+1] + bias[n+1];
            o1.z = cy[j+2] + bias[n+2]; o1.w = cy[j+3] + bias[n+3];
            *(float4*)(C + (size_t)r0 * NT + n)       = o0;
            *(float4*)(C + (size_t)(r0 + 1) * NT + n) = o1;
        }
    }
}

// ---------------- VQ: pipelined distance GEMM + fused argmin ---------------
__global__ __launch_bounds__(256, 2)
void vq_kernel() {
    __shared__ float sm[12288];
    const uint32_t smb = smem_u32(sm);
    const int tid = threadIdx.x;
    const int ty  = tid >> 4;
    const int tx  = tid & 15;
    const int half = blockIdx.y, m0 = blockIdx.x * 128;

    const float* __restrict__ AT = g_hT + (size_t)(half * DDIM) * MROWS + m0;
    const float* __restrict__ BT = &g_eTd[half][0][0];
    const float* __restrict__ bn = &g_bn[half][0];

    float am[8];
#pragma unroll
    for (int i = 0; i < 8; i++) am[i] = g_a[half][m0 + ty * 8 + i];

    float best[8]; int bidx[8];
#pragma unroll
    for (int i = 0; i < 8; i++) { best[i] = __int_as_float(0x7f800000); bidx[i] = 0; }

    auto issue = [&](int c) {
        const int nt = c >> 4, kc = c & 15;
        uint32_t base = smb + (uint32_t)((c & 1) * 6144) * 4;
#pragma unroll
        for (int i = 0; i < 2; i++) {
            int f = tid + i * 256; int k = f >> 5, c4 = f & 31;
            cp16(base + (uint32_t)(k * 128 + c4 * 4) * 4,
                 AT + (size_t)(kc * 16 + k) * MROWS + c4 * 4);
        }
#pragma unroll
        for (int i = 0; i < 4; i++) {
            int f = tid + i * 256; int k = f >> 6, c4 = f & 63;
            cp16(base + (uint32_t)(2048 + k * 256 + c4 * 4) * 4,
                 BT + (size_t)(kc * 16 + k) * (2 * KCODES) + 2 * (nt * 128) + c4 * 4);
        }
        cp_commit();
    };

    u64 acc2[4][8];
    const u64 Z = pk(0.0f, 0.0f);
    const int NCH = (KCODES / 128) * 16;   // 512 chunks

    issue(0);
    for (int c = 0; c < NCH; c++) {
        if (c + 1 < NCH) { issue(c + 1); cp_wait<1>(); } else { cp_wait<0>(); }
        __syncthreads();
        const int kc = c & 15;
        if (kc == 0) {
#pragma unroll
            for (int ip = 0; ip < 4; ip++)
#pragma unroll
                for (int j = 0; j < 8; j++) acc2[ip][j] = Z;
        }
        const float* buf = sm + (c & 1) * 6144;
#pragma unroll
        for (int k = 0; k < 16; k++)
            fma_slice(acc2, buf + k * 128 + ty * 8, buf + 2048 + k * 256 + tx * 16);
        if (kc == 15) {
            const int n0 = (c >> 4) * 128;
            float bnv[8];
#pragma unroll
            for (int j = 0; j < 8; j++) bnv[j] = __ldg(bn + n0 + tx * 8 + j);
#pragma unroll
            for (int ip = 0; ip < 4; ip++) {
                int i0 = 2 * ip, i1 = 2 * ip + 1;
#pragma unroll
                for (int j = 0; j < 8; j++) {
                    float dx, dy;
                    upk(acc2[ip][j], dx, dy);
                    int col = n0 + tx * 8 + j;
                    float t0 = __fadd_rn(am[i0], bnv[j]);
                    float d0 = __fadd_rn(t0, -__fmul_rn(2.0f, dx));
                    if (d0 < best[i0]) { best[i0] = d0; bidx[i0] = col; }
                    float t1 = __fadd_rn(am[i1], bnv[j]);
                    float d1 = __fadd_rn(t1, -__fmul_rn(2.0f, dy));
                    if (d1 < best[i1]) { best[i1] = d1; bidx[i1] = col; }
                }
            }
        }
        __syncthreads();
    }

    // reduction, overlaid on smem buffers
    float* sS = sm;                  // [128][16]
    int*   sI = (int*)(sm + 2048);   // [128][16]
#pragma unroll
    for (int i = 0; i < 8; i++) {
        sS[(ty * 8 + i) * 16 + tx] = best[i];
        sI[(ty * 8 + i) * 16 + tx] = bidx[i];
    }
    __syncthreads();
    if (tid < 128) {
        float b = sS[tid * 16]; int bi = sI[tid * 16];
#pragma unroll
        for (int t = 1; t < 16; t++) {
            float s = sS[tid * 16 + t]; int si = sI[tid * 16 + t];
            if (s < b || (s == b && si < bi)) { b = s; bi = si; }
        }
        g_p[half][m0 + tid]   = b;
        g_idx[half][m0 + tid] = bi;
    }
}

// ---------------- idx + loss outputs ----------------
__global__ void finalize_kernel(float* __restrict__ out) {
    int m = blockIdx.x * blockDim.x + threadIdx.x;
    if (m >= MROWS) return;
    const size_t ZQ = (size_t)MROWS * ODIM;
    out[ZQ + m]             = (float)g_idx[0][m];
    out[ZQ + MROWS + m]     = (float)g_idx[1][m];
    float m1 = __fmul_rn(g_p[0][m], 1.0f / 256.0f);
    float m2 = __fmul_rn(g_p[1][m], 1.0f / 256.0f);
    float l1 = __fadd_rn(m1, __fmul_rn(0.25f, m1));
    float l2 = __fadd_rn(m2, __fmul_rn(0.25f, m2));
    out[ZQ + 2 * (size_t)MROWS + m] = __fmul_rn(0.5f, __fadd_rn(l1, l2));
}

// ---------------- launch ----------------
extern "C" void kernel_launch(void* const* d_in, const int* in_sizes, int n_in,
                              void* d_out, int out_size) {
    (void)in_sizes; (void)n_in; (void)out_size;
    const float* z    = (const float*)d_in[0];
    const float* Wqa  = (const float*)d_in[1];
    const float* bqa  = (const float*)d_in[2];
    const float* emb1 = (const float*)d_in[3];
    const float* emb2 = (const float*)d_in[4];
    const float* Wpq  = (const float*)d_in[5];
    const float* bpq  = (const float*)d_in[6];
    float* out = (float*)d_out;

    // input-only prep
    norms_kernel<<<(2 * KCODES * 32 + 255) / 256, 256>>>(emb1, emb2);
    transposeEdup_kernel<<<dim3(KCODES / 32, DDIM / 32, 2), dim3(32, 8)>>>(emb1, emb2);
    dupW1_kernel<<<(INDIM * HDIM + 255) / 256, 256>>>(Wqa);
    dupW2_kernel<<<(HDIM * ODIM + 255) / 256, 256>>>(Wpq);
    transposeZ_kernel<<<dim3(MROWS / 32, INDIM / 32), dim3(32, 8)>>>(z);

    // GEMM1: g_h = z @ W_qa + b_qa  (operands resolved device-side)
    gemm_pipe<INDIM, HDIM, 0><<<dim3(MROWS / 128, HDIM / 128), 256>>>(bqa, nullptr);

    transposeH_kernel<<<dim3(MROWS / 32, HDIM / 32), dim3(32, 8)>>>();
    rownorm_kernel<<<(MROWS * 32 + 255) / 256, 256>>>();

    vq_kernel<<<dim3(MROWS / 128, 2), 256>>>();

    finalize_kernel<<<(MROWS + 255) / 256, 256>>>(out);

    zqT_kernel<<<dim3(MROWS / 32, HDIM / 32), dim3(32, 8)>>>(emb1, emb2);

    // GEMM2: out = zq_st @ W_pq + b_pq
    gemm_pipe<HDIM, ODIM, 1><<<dim3(MROWS / 128, ODIM / 128), 256>>>(bpq, out);
}

// round 11
// speedup vs baseline: 3.0247x; 3.0247x over previous
#include <cuda_runtime.h>
#include <cstdint>

#define MROWS  16384
#define INDIM  1024
#define HDIM   512
#define DDIM   256
#define KCODES 4096
#define ODIM   1024

typedef unsigned long long u64;

// ---------------- scratch (static device globals; no allocations) ----------
__device__ float g_h[(size_t)MROWS * HDIM];    // h = z @ W_qa + b_qa
__device__ float g_hT[(size_t)HDIM * MROWS];   // h transposed [kk][m]
__device__ float g_zT[(size_t)INDIM * MROWS];  // z transposed [k][m]
__device__ float g_zqT[(size_t)HDIM * MROWS];  // zq_st transposed [kk][m]
__device__ float g_eT[2][DDIM][KCODES];        // emb transposed [half][k][n]
__device__ float g_a[2][MROWS];                // |z_half|^2 per row
__device__ float g_bn[2][KCODES];              // |emb_k|^2 per code
__device__ int   g_idx[2][MROWS];              // argmin indices
__device__ float g_p[2][MROWS];                // winning squared distance

// ---------------- f32x2 helpers ----------------
__device__ __forceinline__ u64 pk(float x, float y) {
    u64 r; asm("mov.b64 %0, {%1, %2};" : "=l"(r) : "f"(x), "f"(y)); return r;
}
__device__ __forceinline__ void upk(u64 v, float& x, float& y) {
    asm("mov.b64 {%0, %1}, %2;" : "=f"(x), "=f"(y) : "l"(v));
}
__device__ __forceinline__ void ffma2(u64& d, u64 a, u64 b) {
    asm("fma.rn.f32x2 %0, %1, %2, %0;" : "+l"(d) : "l"(a), "l"(b));
}
__device__ __forceinline__ uint32_t smem_u32(const void* p) {
    uint32_t a;
    asm("{ .reg .u64 t; cvta.to.shared.u64 t, %1; cvt.u32.u64 %0, t; }" : "=r"(a) : "l"(p));
    return a;
}
__device__ __forceinline__ void cp16(uint32_t dst, const void* src) {
    asm volatile("cp.async.ca.shared.global [%0], [%1], 16;" :: "r"(dst), "l"(src));
}
__device__ __forceinline__ void cp_commit() { asm volatile("cp.async.commit_group;"); }
template <int N> __device__ __forceinline__ void cp_wait() {
    asm volatile("cp.async.wait_group %0;" :: "n"(N));
}

// ---------------- round-6 fma_tile: non-dup B, packing movs ----------------
__device__ __forceinline__ void fma_tile(u64 acc2[4][8],
                                         float4 a0, float4 a1,
                                         float4 b0, float4 b1) {
    u64 av[4] = { pk(a0.x, a0.y), pk(a0.z, a0.w), pk(a1.x, a1.y), pk(a1.z, a1.w) };
    float rb[8] = { b0.x, b0.y, b0.z, b0.w, b1.x, b1.y, b1.z, b1.w };
    u64 bd[8];
#pragma unroll
    for (int j = 0; j < 8; j++) bd[j] = pk(rb[j], rb[j]);
#pragma unroll
    for (int ip = 0; ip < 4; ip++)
#pragma unroll
        for (int j = 0; j < 8; j++) ffma2(acc2[ip][j], av[ip], bd[j]);
}

// ---------------- prep kernels ----------------
__global__ void norms_kernel(const float* __restrict__ emb1,
                             const float* __restrict__ emb2) {
    int gw   = (blockIdx.x * blockDim.x + threadIdx.x) >> 5;
    int lane = threadIdx.x & 31;
    if (gw >= 2 * KCODES) return;
    int half = gw >> 12;
    int k    = gw & (KCODES - 1);
    const float* row = (half ? emb2 : emb1) + (size_t)k * DDIM;
    float s = 0.0f;
    for (int c = lane; c < DDIM; c += 32) { float v = row[c]; s = __fmaf_rn(v, v, s); }
#pragma unroll
    for (int o = 16; o; o >>= 1) s += __shfl_xor_sync(0xffffffffu, s, o);
    if (lane == 0) g_bn[half][k] = s;
}

__global__ void rownorm_kernel() {
    int gw   = (blockIdx.x * blockDim.x + threadIdx.x) >> 5;
    int lane = threadIdx.x & 31;
    if (gw >= MROWS) return;
    const float* row = g_h + (size_t)gw * HDIM;
#pragma unroll
    for (int half = 0; half < 2; half++) {
        float s = 0.0f;
        for (int c = lane; c < DDIM; c += 32) {
            float v = row[half * DDIM + c];
            s = __fmaf_rn(v, v, s);
        }
#pragma unroll
        for (int o = 16; o; o >>= 1) s += __shfl_xor_sync(0xffffffffu, s, o);
        if (lane == 0) g_a[half][gw] = s;
    }
}

__global__ void transposeH_kernel() {            // g_hT[kk][m] = g_h[m][kk]
    __shared__ float t[32][33];
    int m0 = blockIdx.x * 32, k0 = blockIdx.y * 32;
    int x = threadIdx.x, y = threadIdx.y;
#pragma unroll
    for (int r = 0; r < 32; r += 8)
        t[y + r][x] = g_h[(size_t)(m0 + y + r) * HDIM + k0 + x];
    __syncthreads();
#pragma unroll
    for (int r = 0; r < 32; r += 8)
        g_hT[(size_t)(k0 + y + r) * MROWS + m0 + x] = t[x][y + r];
}

__global__ void transposeZ_kernel(const float* __restrict__ z) {
    __shared__ float t[32][33];
    int m0 = blockIdx.x * 32, k0 = blockIdx.y * 32;
    int x = threadIdx.x, y = threadIdx.y;
#pragma unroll
    for (int r = 0; r < 32; r += 8)
        t[y + r][x] = z[(size_t)(m0 + y + r) * INDIM + k0 + x];
    __syncthreads();
#pragma unroll
    for (int r = 0; r < 32; r += 8)
        g_zT[(size_t)(k0 + y + r) * MROWS + m0 + x] = t[x][y + r];
}

// zq_st transposed: g_zqT[kk][m] = h + fp32(e - h)
__global__ void zqT_kernel(const float* __restrict__ emb1,
                           const float* __restrict__ emb2) {
    __shared__ float t[32][33];
    int m0 = blockIdx.x * 32, k0 = blockIdx.y * 32;
    int half = k0 >> 8;
    const float* E = half ? emb2 : emb1;
    int x = threadIdx.x, y = threadIdx.y;
#pragma unroll
    for (int r = 0; r < 32; r += 8) {
        int m = m0 + y + r;
        int idx = g_idx[half][m];
        float h = g_h[(size_t)m * HDIM + k0 + x];
        float e = E[(size_t)idx * DDIM + (k0 - half * DDIM) + x];
        t[y + r][x] = __fadd_rn(h, __fadd_rn(e, -h));
    }
    __syncthreads();
#pragma unroll
    for (int r = 0; r < 32; r += 8)
        g_zqT[(size_t)(k0 + y + r) * MROWS + m0 + x] = t[x][y + r];
}

__global__ void transposeE_kernel(const float* __restrict__ emb1,
                                  const float* __restrict__ emb2) {
    __shared__ float t[32][33];
    int n0 = blockIdx.x * 32, k0 = blockIdx.y * 32, half = blockIdx.z;
    const float* E = half ? emb2 : emb1;
    int x = threadIdx.x, y = threadIdx.y;
#pragma unroll
    for (int r = 0; r < 32; r += 8)
        t[y + r][x] = E[(size_t)(n0 + y + r) * DDIM + k0 + x];
    __syncthreads();
#pragma unroll
    for (int r = 0; r < 32; r += 8)
        g_eT[half][k0 + y + r][n0 + x] = t[x][y + r];
}

// ---------------- pipelined GEMM: C = AT^T @ W + bias ----------------------
// AT k-major [K][MROWS] (device symbol, SEL-resolved); W k-major input [K][NT].
// CTA tile 128x128, k-chunk 16, double buffer (A 2048 + B 2048 floats each).
// SEL=0: AT=g_zT,  C=g_h.   SEL=1: AT=g_zqT, C=Cout.
template <int K, int NT, int SEL>
__global__ __launch_bounds__(256, 2)
void gemm_pipe(const float* __restrict__ W, const float* __restrict__ bias,
               float* __restrict__ Cout) {
    const float* __restrict__ AT = (SEL == 0) ? g_zT : g_zqT;
    float* __restrict__ C = (SEL == 0) ? g_h : Cout;

    __shared__ float sm[8192];
    const uint32_t smb = smem_u32(sm);
    const int tid = threadIdx.x;
    const int ty  = tid >> 4;
    const int tx  = tid & 15;
    const int m0  = blockIdx.x * 128;
    const int n0  = blockIdx.y * 128;
    const int NCH = K / 16;

    auto issue = [&](int c) {
        uint32_t base = smb + (uint32_t)((c & 1) * 4096) * 4;
        const int k = tid >> 5, c4 = tid & 31;       // 8 rows per pass
#pragma unroll
        for (int i = 0; i < 2; i++) {
            int kk = k + i * 8;
            cp16(base + (uint32_t)(kk * 128 + c4 * 4) * 4,
                 AT + (size_t)(c * 16 + kk) * MROWS + m0 + c4 * 4);
            cp16(base + (uint32_t)(2048 + kk * 128 + c4 * 4) * 4,
                 W + (size_t)(c * 16 + kk) * NT + n0 + c4 * 4);
        }
        cp_commit();
    };

    u64 acc2[4][8];
    const u64 Z = pk(0.0f, 0.0f);
#pragma unroll
    for (int ip = 0; ip < 4; ip++)
#pragma unroll
        for (int j = 0; j < 8; j++) acc2[ip][j] = Z;

    issue(0);
    for (int c = 0; c < NCH; c++) {
        if (c + 1 < NCH) { issue(c + 1); cp_wait<1>(); } else { cp_wait<0>(); }
        __syncthreads();
        const float* buf = sm + (c & 1) * 4096;
#pragma unroll
        for (int k = 0; k < 16; k++) {
            float4 a0 = *(const float4*)(buf + k * 128 + ty * 8);
            float4 a1 = *(const float4*)(buf + k * 128 + ty * 8 + 4);
            float4 b0 = *(const float4*)(buf + 2048 + k * 128 + tx * 8);
            float4 b1 = *(const float4*)(buf + 2048 + k * 128 + tx * 8 + 4);
            fma_tile(acc2, a0, a1, b0, b1);
        }
        __syncthreads();
    }

#pragma unroll
    for (int ip = 0; ip < 4; ip++) {
        float cx[8], cy[8];
#pragma unroll
        for (int j = 0; j < 8; j++) upk(acc2[ip][j], cx[j], cy[j]);
        int r0 = m0 + ty * 8 + 2 * ip;
#pragma unroll
        for (int j = 0; j < 8; j += 4) {
            int n = n0 + tx * 8 + j;
            float4 o0, o1;
            o0.x = cx[j+0] + bias[n+0]; o0.y = cx[j+1] + bias[n+1];
            o0.z = cx[j+2] + bias[n+2]; o0.w = cx[j+3] + bias[n+3];
            o1.x = cy[j+0] + bias[n+0]; o1.y = cy[j+1] + bias[n+1];
            o1.z = cy[j+2] + bias[n+2]; o1.w = cy[j+3] + bias[n+3];
            *(float4*)(C + (size_t)r0 * NT + n)       = o0;
            *(float4*)(C + (size_t)(r0 + 1) * NT + n) = o1;
        }
    }
}

// ---------------- VQ (round-6 verbatim): pipelined + fused argmin ----------
__global__ __launch_bounds__(256, 2)
void vq_kernel() {
    __shared__ float sm[8192];   // buf b: A at b*4096, B at b*4096+2048
    const uint32_t smb = smem_u32(sm);
    const int tid = threadIdx.x;
    const int ty  = tid >> 4;
    const int tx  = tid & 15;
    const int half = blockIdx.y, m0 = blockIdx.x * 128;

    const float* __restrict__ AT = g_hT + (size_t)(half * DDIM) * MROWS + m0;
    const float* __restrict__ BT = &g_eT[half][0][0];
    const float* __restrict__ bn = &g_bn[half][0];

    float am[8];
#pragma unroll
    for (int i = 0; i < 8; i++) am[i] = g_a[half][m0 + ty * 8 + i];

    float best[8]; int bidx[8];
#pragma unroll
    for (int i = 0; i < 8; i++) { best[i] = __int_as_float(0x7f800000); bidx[i] = 0; }

    auto issue = [&](int c) {
        const int nt = c >> 4, kc = c & 15;
        const int n0 = nt * 128;
        const float* Asrc = AT + (size_t)(kc * 16) * MROWS;
        const float* Bsrc = BT + (size_t)(kc * 16) * KCODES + n0;
        uint32_t ab = smb + (uint32_t)((c & 1) * 4096) * 4;
        uint32_t bb = ab + 2048 * 4;
#pragma unroll
        for (int i = 0; i < 2; i++) {
            int f = tid + i * 256;
            int k = f >> 5, c4 = f & 31;
            cp16(ab + (uint32_t)(k * 128 + c4 * 4) * 4, Asrc + (size_t)k * MROWS + c4 * 4);
            cp16(bb + (uint32_t)(k * 128 + c4 * 4) * 4, Bsrc + (size_t)k * KCODES + c4 * 4);
        }
        cp_commit();
    };

    u64 acc2[4][8];
    const u64 Z = pk(0.0f, 0.0f);
    const int NCH = (KCODES / 128) * 16;   // 512 chunks

    issue(0);
    for (int c = 0; c < NCH; c++) {
        if (c + 1 < NCH) { issue(c + 1); cp_wait<1>(); } else { cp_wait<0>(); }
        __syncthreads();
        const int kc = c & 15;
        if (kc == 0) {
#pragma unroll
            for (int ip = 0; ip < 4; ip++)
#pragma unroll
                for (int j = 0; j < 8; j++) acc2[ip][j] = Z;
        }
        const float* buf = sm + (c & 1) * 4096;
#pragma unroll
        for (int k = 0; k < 16; k++) {
            float4 a0 = *(const float4*)(buf + k * 128 + ty * 8);
            float4 a1 = *(const float4*)(buf + k * 128 + ty * 8 + 4);
            float4 b0 = *(const float4*)(buf + 2048 + k * 128 + tx * 8);
            float4 b1 = *(const float4*)(buf + 2048 + k * 128 + tx * 8 + 4);
            fma_tile(acc2, a0, a1, b0, b1);
        }
        if (kc == 15) {
            const int n0 = (c >> 4) * 128;
            float bnv[8];
#pragma unroll
            for (int j = 0; j < 8; j++) bnv[j] = __ldg(bn + n0 + tx * 8 + j);
#pragma unroll
            for (int ip = 0; ip < 4; ip++) {
                int i0 = 2 * ip, i1 = 2 * ip + 1;
#pragma unroll
                for (int j = 0; j < 8; j++) {
                    float dx, dy;
                    upk(acc2[ip][j], dx, dy);
                    int col = n0 + tx * 8 + j;
                    float t0 = __fadd_rn(am[i0], bnv[j]);
                    float d0 = __fadd_rn(t0, -__fmul_rn(2.0f, dx));
                    if (d0 < best[i0]) { best[i0] = d0; bidx[i0] = col; }
                    float t1 = __fadd_rn(am[i1], bnv[j]);
                    float d1 = __fadd_rn(t1, -__fmul_rn(2.0f, dy));
                    if (d1 < best[i1]) { best[i1] = d1; bidx[i1] = col; }
                }
            }
        }
        __syncthreads();
    }

    // reduction, overlaid on smem buffers
    float* sS = sm;                  // [128][16]
    int*   sI = (int*)(sm + 2048);   // [128][16]
#pragma unroll
    for (int i = 0; i < 8; i++) {
        sS[(ty * 8 + i) * 16 + tx] = best[i];
        sI[(ty * 8 + i) * 16 + tx] = bidx[i];
    }
    __syncthreads();
    if (tid < 128) {
        float b = sS[tid * 16]; int bi = sI[tid * 16];
#pragma unroll
        for (int t = 1; t < 16; t++) {
            float s = sS[tid * 16 + t]; int si = sI[tid * 16 + t];
            if (s < b || (s == b && si < bi)) { b = s; bi = si; }
        }
        g_p[half][m0 + tid]   = b;
        g_idx[half][m0 + tid] = bi;
    }
}

// ---------------- idx + loss outputs ----------------
__global__ void finalize_kernel(float* __restrict__ out) {
    int m = blockIdx.x * blockDim.x + threadIdx.x;
    if (m >= MROWS) return;
    const size_t ZQ = (size_t)MROWS * ODIM;
    out[ZQ + m]             = (float)g_idx[0][m];
    out[ZQ + MROWS + m]     = (float)g_idx[1][m];
    float m1 = __fmul_rn(g_p[0][m], 1.0f / 256.0f);
    float m2 = __fmul_rn(g_p[1][m], 1.0f / 256.0f);
    float l1 = __fadd_rn(m1, __fmul_rn(0.25f, m1));
    float l2 = __fadd_rn(m2, __fmul_rn(0.25f, m2));
    out[ZQ + 2 * (size_t)MROWS + m] = __fmul_rn(0.5f, __fadd_rn(l1, l2));
}

// ---------------- launch ----------------
extern "C" void kernel_launch(void* const* d_in, const int* in_sizes, int n_in,
                              void* d_out, int out_size) {
    (void)in_sizes; (void)n_in; (void)out_size;
    const float* z    = (const float*)d_in[0];
    const float* Wqa  = (const float*)d_in[1];
    const float* bqa  = (const float*)d_in[2];
    const float* emb1 = (const float*)d_in[3];
    const float* emb2 = (const float*)d_in[4];
    const float* Wpq  = (const float*)d_in[5];
    const float* bpq  = (const float*)d_in[6];
    float* out = (float*)d_out;

    // input-only prep
    norms_kernel<<<(2 * KCODES * 32 + 255) / 256, 256>>>(emb1, emb2);
    transposeE_kernel<<<dim3(KCODES / 32, DDIM / 32, 2), dim3(32, 8)>>>(emb1, emb2);
    transposeZ_kernel<<<dim3(MROWS / 32, INDIM / 32), dim3(32, 8)>>>(z);

    // GEMM1: g_h = z @ W_qa + b_qa
    gemm_pipe<INDIM, HDIM, 0><<<dim3(MROWS / 128, HDIM / 128), 256>>>(Wqa, bqa, nullptr);

    transposeH_kernel<<<dim3(MROWS / 32, HDIM / 32), dim3(32, 8)>>>();
    rownorm_kernel<<<(MROWS * 32 + 255) / 256, 256>>>();

    vq_kernel<<<dim3(MROWS / 128, 2), 256>>>();

    finalize_kernel<<<(MROWS + 255) / 256, 256>>>(out);

    zqT_kernel<<<dim3(MROWS / 32, HDIM / 32), dim3(32, 8)>>>(emb1, emb2);

    // GEMM2: out = zq_st @ W_pq + b_pq
    gemm_pipe<HDIM, ODIM, 1><<<dim3(MROWS / 128, ODIM / 128), 256>>>(Wpq, bpq, out);
}

// round 12
// speedup vs baseline: 3.0390x; 1.0047x over previous
#include <cuda_runtime.h>
#include <cstdint>

#define MROWS  16384
#define INDIM  1024
#define HDIM   512
#define DDIM   256
#define KCODES 4096
#define ODIM   1024

typedef unsigned long long u64;

// ---------------- scratch (static device globals; no allocations) ----------
__device__ float g_h[(size_t)MROWS * HDIM];    // h = z @ W_qa + b_qa
__device__ float g_hT[(size_t)HDIM * MROWS];   // h transposed [kk][m]
__device__ float g_zT[(size_t)INDIM * MROWS];  // z transposed [k][m]
__device__ float g_zqT[(size_t)HDIM * MROWS];  // zq_st transposed [kk][m]
__device__ float g_eT[2][DDIM][KCODES];        // emb transposed [half][k][n]
__device__ float g_a[2][MROWS];                // |z_half|^2 per row
__device__ float g_bn[2][KCODES];              // |emb_k|^2 per code
__device__ int   g_idx[2][MROWS];              // argmin indices
__device__ float g_p[2][MROWS];                // winning squared distance

// ---------------- f32x2 helpers ----------------
__device__ __forceinline__ u64 pk(float x, float y) {
    u64 r; asm("mov.b64 %0, {%1, %2};" : "=l"(r) : "f"(x), "f"(y)); return r;
}
__device__ __forceinline__ void upk(u64 v, float& x, float& y) {
    asm("mov.b64 {%0, %1}, %2;" : "=f"(x), "=f"(y) : "l"(v));
}
__device__ __forceinline__ void ffma2(u64& d, u64 a, u64 b) {
    asm("fma.rn.f32x2 %0, %1, %2, %0;" : "+l"(d) : "l"(a), "l"(b));
}
__device__ __forceinline__ uint32_t smem_u32(const void* p) {
    uint32_t a;
    asm("{ .reg .u64 t; cvta.to.shared.u64 t, %1; cvt.u32.u64 %0, t; }" : "=r"(a) : "l"(p));
    return a;
}
__device__ __forceinline__ void cp16(uint32_t dst, const void* src) {
    asm volatile("cp.async.ca.shared.global [%0], [%1], 16;" :: "r"(dst), "l"(src));
}
__device__ __forceinline__ void cp_commit() { asm volatile("cp.async.commit_group;"); }
template <int N> __device__ __forceinline__ void cp_wait() {
    asm volatile("cp.async.wait_group %0;" :: "n"(N));
}

// ---------------- fma_slice: A direct-packed u64 loads, B register dup -----
// A slice layout [k][128]: row pairs are adjacent floats -> packed operand free.
// Values & k-order identical to round 11 -> bit-exact.
__device__ __forceinline__ void fma_slice(u64 acc2[4][8],
                                          const float* __restrict__ Arow,
                                          const float* __restrict__ Brow) {
    ulonglong2 a01 = *(const ulonglong2*)(Arow);       // rows (0,1),(2,3)
    ulonglong2 a23 = *(const ulonglong2*)(Arow + 4);   // rows (4,5),(6,7)
    u64 av[4] = { a01.x, a01.y, a23.x, a23.y };
    float4 b0 = *(const float4*)(Brow);
    float4 b1 = *(const float4*)(Brow + 4);
    float rb[8] = { b0.x, b0.y, b0.z, b0.w, b1.x, b1.y, b1.z, b1.w };
    u64 bd[8];
#pragma unroll
    for (int j = 0; j < 8; j++) bd[j] = pk(rb[j], rb[j]);
#pragma unroll
    for (int ip = 0; ip < 4; ip++)
#pragma unroll
        for (int j = 0; j < 8; j++) ffma2(acc2[ip][j], av[ip], bd[j]);
}

// ---------------- prep kernels ----------------
__global__ void norms_kernel(const float* __restrict__ emb1,
                             const float* __restrict__ emb2) {
    int gw   = (blockIdx.x * blockDim.x + threadIdx.x) >> 5;
    int lane = threadIdx.x & 31;
    if (gw >= 2 * KCODES) return;
    int half = gw >> 12;
    int k    = gw & (KCODES - 1);
    const float* row = (half ? emb2 : emb1) + (size_t)k * DDIM;
    float s = 0.0f;
    for (int c = lane; c < DDIM; c += 32) { float v = row[c]; s = __fmaf_rn(v, v, s); }
#pragma unroll
    for (int o = 16; o; o >>= 1) s += __shfl_xor_sync(0xffffffffu, s, o);
    if (lane == 0) g_bn[half][k] = s;
}

__global__ void rownorm_kernel() {
    int gw   = (blockIdx.x * blockDim.x + threadIdx.x) >> 5;
    int lane = threadIdx.x & 31;
    if (gw >= MROWS) return;
    const float* row = g_h + (size_t)gw * HDIM;
#pragma unroll
    for (int half = 0; half < 2; half++) {
        float s = 0.0f;
        for (int c = lane; c < DDIM; c += 32) {
            float v = row[half * DDIM + c];
            s = __fmaf_rn(v, v, s);
        }
#pragma unroll
        for (int o = 16; o; o >>= 1) s += __shfl_xor_sync(0xffffffffu, s, o);
        if (lane == 0) g_a[half][gw] = s;
    }
}

__global__ void transposeH_kernel() {            // g_hT[kk][m] = g_h[m][kk]
    __shared__ float t[32][33];
    int m0 = blockIdx.x * 32, k0 = blockIdx.y * 32;
    int x = threadIdx.x, y = threadIdx.y;
#pragma unroll
    for (int r = 0; r < 32; r += 8)
        t[y + r][x] = g_h[(size_t)(m0 + y + r) * HDIM + k0 + x];
    __syncthreads();
#pragma unroll
    for (int r = 0; r < 32; r += 8)
        g_hT[(size_t)(k0 + y + r) * MROWS + m0 + x] = t[x][y + r];
}

__global__ void transposeZ_kernel(const float* __restrict__ z) {
    __shared__ float t[32][33];
    int m0 = blockIdx.x * 32, k0 = blockIdx.y * 32;
    int x = threadIdx.x, y = threadIdx.y;
#pragma unroll
    for (int r = 0; r < 32; r += 8)
        t[y + r][x] = z[(size_t)(m0 + y + r) * INDIM + k0 + x];
    __syncthreads();
#pragma unroll
    for (int r = 0; r < 32; r += 8)
        g_zT[(size_t)(k0 + y + r) * MROWS + m0 + x] = t[x][y + r];
}

// zq_st transposed: g_zqT[kk][m] = h + fp32(e - h)
__global__ void zqT_kernel(const float* __restrict__ emb1,
                           const float* __restrict__ emb2) {
    __shared__ float t[32][33];
    int m0 = blockIdx.x * 32, k0 = blockIdx.y * 32;
    int half = k0 >> 8;
    const float* E = half ? emb2 : emb1;
    int x = threadIdx.x, y = threadIdx.y;
#pragma unroll
    for (int r = 0; r < 32; r += 8) {
        int m = m0 + y + r;
        int idx = g_idx[half][m];
        float h = g_h[(size_t)m * HDIM + k0 + x];
        float e = E[(size_t)idx * DDIM + (k0 - half * DDIM) + x];
        t[y + r][x] = __fadd_rn(h, __fadd_rn(e, -h));
    }
    __syncthreads();
#pragma unroll
    for (int r = 0; r < 32; r += 8)
        g_zqT[(size_t)(k0 + y + r) * MROWS + m0 + x] = t[x][y + r];
}

__global__ void transposeE_kernel(const float* __restrict__ emb1,
                                  const float* __restrict__ emb2) {
    __shared__ float t[32][33];
    int n0 = blockIdx.x * 32, k0 = blockIdx.y * 32, half = blockIdx.z;
    const float* E = half ? emb2 : emb1;
    int x = threadIdx.x, y = threadIdx.y;
#pragma unroll
    for (int r = 0; r < 32; r += 8)
        t[y + r][x] = E[(size_t)(n0 + y + r) * DDIM + k0 + x];
    __syncthreads();
#pragma unroll
    for (int r = 0; r < 32; r += 8)
        g_eT[half][k0 + y + r][n0 + x] = t[x][y + r];
}

// ---------------- pipelined GEMM: C = AT^T @ W + bias ----------------------
// 3-stage cp.async ring, ONE __syncthreads per k-chunk.
// SEL=0: AT=g_zT, C=g_h.  SEL=1: AT=g_zqT, C=Cout.
template <int K, int NT, int SEL>
__global__ __launch_bounds__(256, 2)
void gemm_pipe(const float* __restrict__ W, const float* __restrict__ bias,
               float* __restrict__ Cout) {
    const float* __restrict__ AT = (SEL == 0) ? g_zT : g_zqT;
    float* __restrict__ C = (SEL == 0) ? g_h : Cout;

    __shared__ float sm[12288];          // 3 stages x (A 2048 + B 2048)
    const uint32_t smb = smem_u32(sm);
    const int tid = threadIdx.x;
    const int ty  = tid >> 4;
    const int tx  = tid & 15;
    const int m0  = blockIdx.x * 128;
    const int n0  = blockIdx.y * 128;
    const int NCH = K / 16;

    auto issue = [&](int c) {
        uint32_t base = smb + (uint32_t)((c % 3) * 4096) * 4;
        const int k = tid >> 5, c4 = tid & 31;
#pragma unroll
        for (int i = 0; i < 2; i++) {
            int kk = k + i * 8;
            cp16(base + (uint32_t)(kk * 128 + c4 * 4) * 4,
                 AT + (size_t)(c * 16 + kk) * MROWS + m0 + c4 * 4);
            cp16(base + (uint32_t)(2048 + kk * 128 + c4 * 4) * 4,
                 W + (size_t)(c * 16 + kk) * NT + n0 + c4 * 4);
        }
        cp_commit();
    };

    u64 acc2[4][8];
    const u64 Z = pk(0.0f, 0.0f);
#pragma unroll
    for (int ip = 0; ip < 4; ip++)
#pragma unroll
        for (int j = 0; j < 8; j++) acc2[ip][j] = Z;

    issue(0); issue(1);
    for (int c = 0; c < NCH; c++) {
        cp_wait<1>();
        __syncthreads();                 // chunk c data visible; c-1 reads done
        if (c + 2 < NCH) issue(c + 2);   // overwrites buf (c-1)%3 — safe
        const float* buf = sm + (c % 3) * 4096;
#pragma unroll
        for (int k = 0; k < 16; k++)
            fma_slice(acc2, buf + k * 128 + ty * 8, buf + 2048 + k * 128 + tx * 8);
    }

#pragma unroll
    for (int ip = 0; ip < 4; ip++) {
        float cx[8], cy[8];
#pragma unroll
        for (int j = 0; j < 8; j++) upk(acc2[ip][j], cx[j], cy[j]);
        int r0 = m0 + ty * 8 + 2 * ip;
#pragma unroll
        for (int j = 0; j < 8; j += 4) {
            int n = n0 + tx * 8 + j;
            float4 o0, o1;
            o0.x = cx[j+0] + bias[n+0]; o0.y = cx[j+1] + bias[n+1];
            o0.z = cx[j+2] + bias[n+2]; o0.w = cx[j+3] + bias[n+3];
            o1.x = cy[j+0] + bias[n+0]; o1.y = cy[j+1] + bias[n+1];
            o1.z = cy[j+2] + bias[n+2]; o1.w = cy[j+3] + bias[n+3];
            *(float4*)(C + (size_t)r0 * NT + n)       = o0;
            *(float4*)(C + (size_t)(r0 + 1) * NT + n) = o1;
        }
    }
}

// ---------------- VQ: 3-stage pipelined distance GEMM + fused argmin -------
__global__ __launch_bounds__(256, 2)
void vq_kernel() {
    __shared__ float sm[12288];          // 3 stages x (A 2048 + B 2048)
    const uint32_t smb = smem_u32(sm);
    const int tid = threadIdx.x;
    const int ty  = tid >> 4;
    const int tx  = tid & 15;
    const int half = blockIdx.y, m0 = blockIdx.x * 128;

    const float* __restrict__ AT = g_hT + (size_t)(half * DDIM) * MROWS + m0;
    const float* __restrict__ BT = &g_eT[half][0][0];
    const float* __restrict__ bn = &g_bn[half][0];

    float am[8];
#pragma unroll
    for (int i = 0; i < 8; i++) am[i] = g_a[half][m0 + ty * 8 + i];

    float best[8]; int bidx[8];
#pragma unroll
    for (int i = 0; i < 8; i++) { best[i] = __int_as_float(0x7f800000); bidx[i] = 0; }

    auto issue = [&](int c) {
        const int nt = c >> 4, kc = c & 15;
        const float* Asrc = AT + (size_t)(kc * 16) * MROWS;
        const float* Bsrc = BT + (size_t)(kc * 16) * KCODES + nt * 128;
        uint32_t ab = smb + (uint32_t)((c % 3) * 4096) * 4;
        uint32_t bb = ab + 2048 * 4;
        const int k = tid >> 5, c4 = tid & 31;
#pragma unroll
        for (int i = 0; i < 2; i++) {
            int kk = k + i * 8;
            cp16(ab + (uint32_t)(kk * 128 + c4 * 4) * 4, Asrc + (size_t)kk * MROWS + c4 * 4);
            cp16(bb + (uint32_t)(kk * 128 + c4 * 4) * 4, Bsrc + (size_t)kk * KCODES + c4 * 4);
        }
        cp_commit();
    };

    u64 acc2[4][8];
    const u64 Z = pk(0.0f, 0.0f);
    const int NCH = (KCODES / 128) * 16;   // 512 chunks

    issue(0); issue(1);
    for (int c = 0; c < NCH; c++) {
        cp_wait<1>();
        __syncthreads();
        if (c + 2 < NCH) issue(c + 2);
        const int kc = c & 15;
        if (kc == 0) {
#pragma unroll
            for (int ip = 0; ip < 4; ip++)
#pragma unroll
                for (int j = 0; j < 8; j++) acc2[ip][j] = Z;
        }
        const float* buf = sm + (c % 3) * 4096;
#pragma unroll
        for (int k = 0; k < 16; k++)
            fma_slice(acc2, buf + k * 128 + ty * 8, buf + 2048 + k * 128 + tx * 8);
        if (kc == 15) {
            const int n0 = (c >> 4) * 128;
            float bnv[8];
#pragma unroll
            for (int j = 0; j < 8; j++) bnv[j] = __ldg(bn + n0 + tx * 8 + j);
#pragma unroll
            for (int ip = 0; ip < 4; ip++) {
                int i0 = 2 * ip, i1 = 2 * ip + 1;
#pragma unroll
                for (int j = 0; j < 8; j++) {
                    float dx, dy;
                    upk(acc2[ip][j], dx, dy);
                    int col = n0 + tx * 8 + j;
                    float t0 = __fadd_rn(am[i0], bnv[j]);
                    float d0 = __fadd_rn(t0, -__fmul_rn(2.0f, dx));
                    if (d0 < best[i0]) { best[i0] = d0; bidx[i0] = col; }
                    float t1 = __fadd_rn(am[i1], bnv[j]);
                    float d1 = __fadd_rn(t1, -__fmul_rn(2.0f, dy));
                    if (d1 < best[i1]) { best[i1] = d1; bidx[i1] = col; }
                }
            }
        }
    }

    // final reduction (all compute done; reuse smem after a barrier)
    __syncthreads();
    float* sS = sm;                  // [128][16]
    int*   sI = (int*)(sm + 2048);   // [128][16]
#pragma unroll
    for (int i = 0; i < 8; i++) {
        sS[(ty * 8 + i) * 16 + tx] = best[i];
        sI[(ty * 8 + i) * 16 + tx] = bidx[i];
    }
    __syncthreads();
    if (tid < 128) {
        float b = sS[tid * 16]; int bi = sI[tid * 16];
#pragma unroll
        for (int t = 1; t < 16; t++) {
            float s = sS[tid * 16 + t]; int si = sI[tid * 16 + t];
            if (s < b || (s == b && si < bi)) { b = s; bi = si; }
        }
        g_p[half][m0 + tid]   = b;
        g_idx[half][m0 + tid] = bi;
    }
}

// ---------------- idx + loss outputs ----------------
__global__ void finalize_kernel(float* __restrict__ out) {
    int m = blockIdx.x * blockDim.x + threadIdx.x;
    if (m >= MROWS) return;
    const size_t ZQ = (size_t)MROWS * ODIM;
    out[ZQ + m]             = (float)g_idx[0][m];
    out[ZQ + MROWS + m]     = (float)g_idx[1][m];
    float m1 = __fmul_rn(g_p[0][m], 1.0f / 256.0f);
    float m2 = __fmul_rn(g_p[1][m], 1.0f / 256.0f);
    float l1 = __fadd_rn(m1, __fmul_rn(0.25f, m1));
    float l2 = __fadd_rn(m2, __fmul_rn(0.25f, m2));
    out[ZQ + 2 * (size_t)MROWS + m] = __fmul_rn(0.5f, __fadd_rn(l1, l2));
}

// ---------------- launch ----------------
extern "C" void kernel_launch(void* const* d_in, const int* in_sizes, int n_in,
                              void* d_out, int out_size) {
    (void)in_sizes; (void)n_in; (void)out_size;
    const float* z    = (const float*)d_in[0];
    const float* Wqa  = (const float*)d_in[1];
    const float* bqa  = (const float*)d_in[2];
    const float* emb1 = (const float*)d_in[3];
    const float* emb2 = (const float*)d_in[4];
    const float* Wpq  = (const float*)d_in[5];
    const float* bpq  = (const float*)d_in[6];
    float* out = (float*)d_out;

    // input-only prep
    norms_kernel<<<(2 * KCODES * 32 + 255) / 256, 256>>>(emb1, emb2);
    transposeE_kernel<<<dim3(KCODES / 32, DDIM / 32, 2), dim3(32, 8)>>>(emb1, emb2);
    transposeZ_kernel<<<dim3(MROWS / 32, INDIM / 32), dim3(32, 8)>>>(z);

    // GEMM1: g_h = z @ W_qa + b_qa
    gemm_pipe<INDIM, HDIM, 0><<<dim3(MROWS / 128, HDIM / 128), 256>>>(Wqa, bqa, nullptr);

    transposeH_kernel<<<dim3(MROWS / 32, HDIM / 32), dim3(32, 8)>>>();
    rownorm_kernel<<<(MROWS * 32 + 255) / 256, 256>>>();

    vq_kernel<<<dim3(MROWS / 128, 2), 256>>>();

    finalize_kernel<<<(MROWS + 255) / 256, 256>>>(out);

    zqT_kernel<<<dim3(MROWS / 32, HDIM / 32), dim3(32, 8)>>>(emb1, emb2);

    // GEMM2: out = zq_st @ W_pq + b_pq
    gemm_pipe<HDIM, ODIM, 1><<<dim3(MROWS / 128, ODIM / 128), 256>>>(Wpq, bpq, out);
}